// round 8
// baseline (speedup 1.0000x reference)
#include <cuda_runtime.h>
#include <cstdint>

// ---------------- problem constants ----------------
#define D        2048     // EMBED_DIM
#define VQD      256      // VQ_DIM
#define ATO      32000    // added_tokens_offset (text < ATO)
#define NUMLIM   33000    // ATO + SCO
#define TDLIM    33100    // VQ_START / image_token_offset
#define VQEND    49484    // vqgan_end_index
#define NTOK_MAX 65536

// ---------------- scratch (no allocations allowed) ----------------
__device__ int g_cnt;
__device__ int g_pos[NTOK_MAX];
__device__ int g_idx[NTOK_MAX];
__device__ __align__(16) float g_projT[VQD * D];   // [k][d] = proj_w[d][k]

typedef unsigned long long u64;

__device__ __forceinline__ u64 pack2(float lo, float hi) {
    u64 r; asm("mov.b64 %0, {%1,%2};" : "=l"(r) : "f"(lo), "f"(hi)); return r;
}
__device__ __forceinline__ void ffma2(u64 &d, u64 a, u64 b) {
    // packed fp32x2 FMA -> SASS FFMA2 (2x fp32 throughput on sm_103a)
    asm("fma.rn.f32x2 %0, %1, %2, %3;" : "=l"(d) : "l"(a), "l"(b), "l"(d));
}

// ---------------- launch 1: transpose proj_w + zero counter ----------------
__global__ void prep_kernel(const float* __restrict__ proj_w) {
    int i = blockIdx.x * blockDim.x + threadIdx.x;
    if (i == 0) g_cnt = 0;
    if (i < D * VQD) {
        int d = i >> 8;        // proj_w row (embed dim), row length 256
        int k = i & 255;       // vq dim
        g_projT[k * D + d] = proj_w[i];
    }
}

// ---------------- launch 2: classify + gather-copy (warp per token) ----------------
__global__ void classify_copy_kernel(const int* __restrict__ x,
                                     const float4* __restrict__ tok_emb,
                                     const float4* __restrict__ added_emb,
                                     const float4* __restrict__ nums_emb,
                                     float4* __restrict__ out, int n_tok) {
    int gw   = (blockIdx.x * blockDim.x + threadIdx.x) >> 5;   // token index
    int lane = threadIdx.x & 31;
    if (gw >= n_tok) return;
    int t = x[gw];

    const float4* src;
    if (t < ATO) {
        src = tok_emb + (size_t)t * (D / 4);
    } else if (t < NUMLIM) {
        src = nums_emb + (size_t)(t - ATO) * (D / 4);
    } else if (t < TDLIM) {
        src = added_emb + (size_t)(t - NUMLIM) * (D / 4);
    } else if (t < VQEND) {
        // image token: compact into list; GEMM kernel writes its output row
        if (lane == 0) {
            int s = atomicAdd(&g_cnt, 1);
            g_pos[s] = gw;
            g_idx[s] = t - TDLIM;
        }
        return;
    } else {
        src = nullptr;  // out-of-range -> zeros (unreachable with this data, but safe)
    }

    float4* dst = out + (size_t)gw * (D / 4);
    if (src) {
        #pragma unroll
        for (int i = 0; i < (D / 4) / 32; i++)      // 16 float4 per lane
            dst[lane + 32 * i] = src[lane + 32 * i];
    } else {
        float4 z = make_float4(0.f, 0.f, 0.f, 0.f);
        #pragma unroll
        for (int i = 0; i < (D / 4) / 32; i++)
            dst[lane + 32 * i] = z;
    }
}

// ---------------- launch 3: compacted image-token GEMM ----------------
// out[pos[i], :] = codebook[idx[i], :] (1x256)  @  proj_w^T (256x2048)
// Tile: 32 tokens x 256 dims per block; K = 256 in chunks of 8.
// Thread layout: tx = lane (dim group), ty = warp (token group, 4 tokens each).
// Each thread: 4 tokens x 8 dims, accumulated as 4x4 packed f32x2 FFMA2.
#define TT 32
#define TD 256

__global__ __launch_bounds__(256)
void img_gemm_kernel(const float* __restrict__ codebook, float* __restrict__ out,
                     int n_tile_tok) {
    __shared__ float As[TT * VQD];   // 32 KB: gathered codebook rows [token][k]
    __shared__ float Bs[8 * TD];     //  8 KB: projT chunk [kk][d]

    int n_img = g_cnt;
    int t0 = blockIdx.y * TT;
    if (t0 >= n_img) return;               // fixed grid; inactive tiles exit
    int dt = blockIdx.x * TD;

    int tid = threadIdx.x;
    int tx = tid & 31, ty = tid >> 5;

    // gather A: thread handles token tid>>3, segment tid&7 (32 floats = 8 float4)
    {
        int tokl = tid >> 3, seg = tid & 7;
        int gi = t0 + tokl;
        int idx = (gi < n_img) ? g_idx[gi] : 0;
        const float4* srow = (const float4*)(codebook + (size_t)idx * VQD) + seg * 8;
        float4* drow = (float4*)(As + tokl * VQD) + seg * 8;
        #pragma unroll
        for (int i = 0; i < 8; i++) drow[i] = srow[i];
    }

    u64 acc[4][4];
    #pragma unroll
    for (int j = 0; j < 4; j++)
        #pragma unroll
        for (int p = 0; p < 4; p++) acc[j][p] = 0ull;

    const float* bsrc = g_projT + dt;

    for (int k0 = 0; k0 < VQD; k0 += 8) {
        __syncthreads();                    // also orders the As gather (first iter)
        // load Bs[8][256]: 512 float4, 2 per thread, coalesced rows of projT
        #pragma unroll
        for (int i = 0; i < 2; i++) {
            int fi = tid + 256 * i;         // float4 index within chunk
            int kk = fi >> 6;               // 64 float4 per k-row
            int c4 = fi & 63;
            ((float4*)Bs)[fi] = *((const float4*)(bsrc + (size_t)(k0 + kk) * D) + c4);
        }
        __syncthreads();

        #pragma unroll
        for (int kk = 0; kk < 8; kk++) {
            const float* brow = Bs + kk * TD;
            // dims: {2tx, 2tx+1} + 64p  -> conflict-free LDS.64, coalesced STG.64
            u64 b0 = *(const u64*)(brow + 2 * tx);
            u64 b1 = *(const u64*)(brow + 2 * tx + 64);
            u64 b2 = *(const u64*)(brow + 2 * tx + 128);
            u64 b3 = *(const u64*)(brow + 2 * tx + 192);
            int k = k0 + kk;
            #pragma unroll
            for (int j = 0; j < 4; j++) {
                float a = As[(ty * 4 + j) * VQD + k];   // broadcast within warp
                u64 ap = pack2(a, a);
                ffma2(acc[j][0], ap, b0);
                ffma2(acc[j][1], ap, b1);
                ffma2(acc[j][2], ap, b2);
                ffma2(acc[j][3], ap, b3);
            }
        }
    }

    // epilogue: scatter rows to out
    #pragma unroll
    for (int j = 0; j < 4; j++) {
        int gi = t0 + ty * 4 + j;
        if (gi >= n_img) continue;
        int row = g_pos[gi];
        float* op = out + (size_t)row * D + dt;
        *(u64*)(op + 2 * tx)       = acc[j][0];
        *(u64*)(op + 2 * tx + 64)  = acc[j][1];
        *(u64*)(op + 2 * tx + 128) = acc[j][2];
        *(u64*)(op + 2 * tx + 192) = acc[j][3];
    }
}

// ---------------- launcher ----------------
extern "C" void kernel_launch(void* const* d_in, const int* in_sizes, int n_in,
                              void* d_out, int out_size) {
    const int*   x        = (const int*)d_in[0];
    const float* tok_emb  = (const float*)d_in[1];
    const float* added    = (const float*)d_in[2];
    const float* nums     = (const float*)d_in[3];
    const float* codebook = (const float*)d_in[4];
    const float* proj_w   = (const float*)d_in[5];
    float*       out      = (float*)d_out;
    int n_tok = in_sizes[0];                 // B*S = 32768

    prep_kernel<<<(D * VQD + 255) / 256, 256>>>(proj_w);

    classify_copy_kernel<<<(n_tok + 7) / 8, 256>>>(
        x, (const float4*)tok_emb, (const float4*)added,
        (const float4*)nums, (float4*)out, n_tok);

    int n_tile_tok = (n_tok + TT - 1) / TT;  // worst case: all tokens are images
    dim3 grid(D / TD, n_tile_tok);
    img_gemm_kernel<<<grid, 256>>>(codebook, out, n_tile_tok);
}

// round 9
// speedup vs baseline: 1.0001x; 1.0001x over previous
#include <cuda_runtime.h>
#include <cstdint>

// ---------------- problem constants ----------------
#define D        2048     // EMBED_DIM
#define VQD      256      // VQ_DIM
#define ATO      32000    // added_tokens_offset (text < ATO)
#define NUMLIM   33000    // ATO + SCO
#define TDLIM    33100    // VQ_START / image_token_offset
#define VQEND    49484    // vqgan_end_index
#define NTOK_MAX 65536

// ---------------- scratch (no allocations allowed) ----------------
__device__ int g_cnt;
__device__ int g_pos[NTOK_MAX];
__device__ int g_idx[NTOK_MAX];
__device__ __align__(16) float g_projT[VQD * D];   // [k][d] = proj_w[d][k]

typedef unsigned long long u64;

__device__ __forceinline__ u64 pack2(float lo, float hi) {
    u64 r; asm("mov.b64 %0, {%1,%2};" : "=l"(r) : "f"(lo), "f"(hi)); return r;
}
__device__ __forceinline__ void ffma2(u64 &d, u64 a, u64 b) {
    // packed fp32x2 FMA -> SASS FFMA2 (2x fp32 throughput on sm_103a)
    asm("fma.rn.f32x2 %0, %1, %2, %3;" : "=l"(d) : "l"(a), "l"(b), "l"(d));
}

// ---------------- launch 1: transpose proj_w + zero counter ----------------
__global__ void prep_kernel(const float* __restrict__ proj_w) {
    int i = blockIdx.x * blockDim.x + threadIdx.x;
    if (i == 0) g_cnt = 0;
    if (i < D * VQD) {
        int d = i >> 8;        // proj_w row (embed dim), row length 256
        int k = i & 255;       // vq dim
        g_projT[k * D + d] = proj_w[i];
    }
}

// ---------------- launch 2: classify + gather-copy (warp per token) ----------------
__global__ void classify_copy_kernel(const int* __restrict__ x,
                                     const float4* __restrict__ tok_emb,
                                     const float4* __restrict__ added_emb,
                                     const float4* __restrict__ nums_emb,
                                     float4* __restrict__ out, int n_tok) {
    int gw   = (blockIdx.x * blockDim.x + threadIdx.x) >> 5;   // token index
    int lane = threadIdx.x & 31;
    if (gw >= n_tok) return;
    int t = x[gw];

    const float4* src;
    if (t < ATO) {
        src = tok_emb + (size_t)t * (D / 4);
    } else if (t < NUMLIM) {
        src = nums_emb + (size_t)(t - ATO) * (D / 4);
    } else if (t < TDLIM) {
        src = added_emb + (size_t)(t - NUMLIM) * (D / 4);
    } else if (t < VQEND) {
        // image token: compact into list; GEMM kernel writes its output row
        if (lane == 0) {
            int s = atomicAdd(&g_cnt, 1);
            g_pos[s] = gw;
            g_idx[s] = t - TDLIM;
        }
        return;
    } else {
        src = nullptr;  // out-of-range -> zeros (unreachable with this data, but safe)
    }

    float4* dst = out + (size_t)gw * (D / 4);
    if (src) {
        #pragma unroll
        for (int i = 0; i < (D / 4) / 32; i++)      // 16 float4 per lane
            dst[lane + 32 * i] = src[lane + 32 * i];
    } else {
        float4 z = make_float4(0.f, 0.f, 0.f, 0.f);
        #pragma unroll
        for (int i = 0; i < (D / 4) / 32; i++)
            dst[lane + 32 * i] = z;
    }
}

// ---------------- launch 3: compacted image-token GEMM ----------------
// out[pos[i], :] = codebook[idx[i], :] (1x256)  @  proj_w^T (256x2048)
// Tile: 32 tokens x 256 dims per block; K = 256 in chunks of 8.
// Thread layout: tx = lane (dim group), ty = warp (token group, 4 tokens each).
// Each thread: 4 tokens x 8 dims, accumulated as 4x4 packed f32x2 FFMA2.
#define TT 32
#define TD 256

__global__ __launch_bounds__(256)
void img_gemm_kernel(const float* __restrict__ codebook, float* __restrict__ out,
                     int n_tile_tok) {
    __shared__ float As[TT * VQD];   // 32 KB: gathered codebook rows [token][k]
    __shared__ float Bs[8 * TD];     //  8 KB: projT chunk [kk][d]

    int n_img = g_cnt;
    int t0 = blockIdx.y * TT;
    if (t0 >= n_img) return;               // fixed grid; inactive tiles exit
    int dt = blockIdx.x * TD;

    int tid = threadIdx.x;
    int tx = tid & 31, ty = tid >> 5;

    // gather A: thread handles token tid>>3, segment tid&7 (32 floats = 8 float4)
    {
        int tokl = tid >> 3, seg = tid & 7;
        int gi = t0 + tokl;
        int idx = (gi < n_img) ? g_idx[gi] : 0;
        const float4* srow = (const float4*)(codebook + (size_t)idx * VQD) + seg * 8;
        float4* drow = (float4*)(As + tokl * VQD) + seg * 8;
        #pragma unroll
        for (int i = 0; i < 8; i++) drow[i] = srow[i];
    }

    u64 acc[4][4];
    #pragma unroll
    for (int j = 0; j < 4; j++)
        #pragma unroll
        for (int p = 0; p < 4; p++) acc[j][p] = 0ull;

    const float* bsrc = g_projT + dt;

    for (int k0 = 0; k0 < VQD; k0 += 8) {
        __syncthreads();                    // also orders the As gather (first iter)
        // load Bs[8][256]: 512 float4, 2 per thread, coalesced rows of projT
        #pragma unroll
        for (int i = 0; i < 2; i++) {
            int fi = tid + 256 * i;         // float4 index within chunk
            int kk = fi >> 6;               // 64 float4 per k-row
            int c4 = fi & 63;
            ((float4*)Bs)[fi] = *((const float4*)(bsrc + (size_t)(k0 + kk) * D) + c4);
        }
        __syncthreads();

        #pragma unroll
        for (int kk = 0; kk < 8; kk++) {
            const float* brow = Bs + kk * TD;
            // dims: {2tx, 2tx+1} + 64p  -> conflict-free LDS.64, coalesced STG.64
            u64 b0 = *(const u64*)(brow + 2 * tx);
            u64 b1 = *(const u64*)(brow + 2 * tx + 64);
            u64 b2 = *(const u64*)(brow + 2 * tx + 128);
            u64 b3 = *(const u64*)(brow + 2 * tx + 192);
            int k = k0 + kk;
            #pragma unroll
            for (int j = 0; j < 4; j++) {
                float a = As[(ty * 4 + j) * VQD + k];   // broadcast within warp
                u64 ap = pack2(a, a);
                ffma2(acc[j][0], ap, b0);
                ffma2(acc[j][1], ap, b1);
                ffma2(acc[j][2], ap, b2);
                ffma2(acc[j][3], ap, b3);
            }
        }
    }

    // epilogue: scatter rows to out
    #pragma unroll
    for (int j = 0; j < 4; j++) {
        int gi = t0 + ty * 4 + j;
        if (gi >= n_img) continue;
        int row = g_pos[gi];
        float* op = out + (size_t)row * D + dt;
        *(u64*)(op + 2 * tx)       = acc[j][0];
        *(u64*)(op + 2 * tx + 64)  = acc[j][1];
        *(u64*)(op + 2 * tx + 128) = acc[j][2];
        *(u64*)(op + 2 * tx + 192) = acc[j][3];
    }
}

// ---------------- launcher ----------------
extern "C" void kernel_launch(void* const* d_in, const int* in_sizes, int n_in,
                              void* d_out, int out_size) {
    const int*   x        = (const int*)d_in[0];
    const float* tok_emb  = (const float*)d_in[1];
    const float* added    = (const float*)d_in[2];
    const float* nums     = (const float*)d_in[3];
    const float* codebook = (const float*)d_in[4];
    const float* proj_w   = (const float*)d_in[5];
    float*       out      = (float*)d_out;
    int n_tok = in_sizes[0];                 // B*S = 32768

    prep_kernel<<<(D * VQD + 255) / 256, 256>>>(proj_w);

    classify_copy_kernel<<<(n_tok + 7) / 8, 256>>>(
        x, (const float4*)tok_emb, (const float4*)added,
        (const float4*)nums, (float4*)out, n_tok);

    int n_tile_tok = (n_tok + TT - 1) / TT;  // worst case: all tokens are images
    dim3 grid(D / TD, n_tile_tok);
    img_gemm_kernel<<<grid, 256>>>(codebook, out, n_tile_tok);
}